// round 1
// baseline (speedup 1.0000x reference)
#include <cuda_runtime.h>

#define N_NODES 50000
#define N_EDGES 1600000
#define D 128
#define SLOPE 0.01f
#define GEMM_THREADS 512
#define GEMM_SMEM (2 * D * D * 4 + 2 * D * 4)  // two transposed W matrices + biases

// ---------------- scratch (device globals: no allocations allowed) ----------
__device__ int   g_cnt[N_NODES];
__device__ int   g_offs[N_NODES + 1];
__device__ int   g_cursor[N_NODES];
__device__ int   g_ssrc[N_EDGES];
__device__ float g_H[N_NODES * D];

// ---------------- helpers ----------------------------------------------------
__device__ __forceinline__ void fma2(unsigned long long& acc,
                                     unsigned long long a,
                                     unsigned long long b) {
    asm("fma.rn.f32x2 %0, %1, %2, %0;" : "+l"(acc) : "l"(a), "l"(b));
}
__device__ __forceinline__ unsigned long long dup2(float x) {
    unsigned long long r;
    asm("mov.b64 %0, {%1, %1};" : "=l"(r) : "f"(x));
    return r;
}
__device__ __forceinline__ float2 unpack2(unsigned long long v) {
    float2 f;
    asm("mov.b64 {%0, %1}, %2;" : "=f"(f.x), "=f"(f.y) : "l"(v));
    return f;
}
__device__ __forceinline__ float f4c(const float4& v, int c) {
    switch (c) { case 0: return v.x; case 1: return v.y; case 2: return v.z; default: return v.w; }
}
__device__ __forceinline__ float lrelu(float x) { return x > 0.0f ? x : x * SLOPE; }

// ---------------- phase 1: CSR build -----------------------------------------
__global__ void k_zero() {
    int i = blockIdx.x * blockDim.x + threadIdx.x;
    if (i < N_NODES) g_cnt[i] = 0;
}

__global__ void k_count(const int* __restrict__ dst) {
    int i = blockIdx.x * blockDim.x + threadIdx.x;
    if (i < N_EDGES) atomicAdd(&g_cnt[dst[i]], 1);
}

__global__ void k_scan() {
    __shared__ int warpsum[32];
    __shared__ int carry_s;
    int tid = threadIdx.x, lane = tid & 31, wid = tid >> 5;
    if (tid == 0) carry_s = 0;
    __syncthreads();
    for (int base = 0; base < N_NODES; base += 1024) {
        int i = base + tid;
        int v = (i < N_NODES) ? g_cnt[i] : 0;
        int x = v;
        #pragma unroll
        for (int o = 1; o < 32; o <<= 1) {
            int y = __shfl_up_sync(0xffffffffu, x, o);
            if (lane >= o) x += y;
        }
        if (lane == 31) warpsum[wid] = x;
        __syncthreads();
        if (wid == 0) {
            int s = warpsum[lane];
            #pragma unroll
            for (int o = 1; o < 32; o <<= 1) {
                int y = __shfl_up_sync(0xffffffffu, s, o);
                if (lane >= o) s += y;
            }
            warpsum[lane] = s;
        }
        __syncthreads();
        int incl = x + (wid ? warpsum[wid - 1] : 0);
        int excl = incl - v + carry_s;
        if (i < N_NODES) { g_offs[i] = excl; g_cursor[i] = excl; }
        __syncthreads();  // everyone has read carry_s
        if (tid == 1023) carry_s = excl + v;  // = old carry + chunk total
        __syncthreads();
    }
    if (threadIdx.x == 0) g_offs[N_NODES] = carry_s;
}

__global__ void k_fill(const int* __restrict__ src, const int* __restrict__ dst) {
    int i = blockIdx.x * blockDim.x + threadIdx.x;
    if (i < N_EDGES) {
        int p = atomicAdd(&g_cursor[dst[i]], 1);
        g_ssrc[p] = src[i];
    }
}

// ---------------- phase 2: gather-sum (one warp per node) --------------------
__global__ void k_gather(const float4* __restrict__ E4) {
    int w = (blockIdx.x * blockDim.x + threadIdx.x) >> 5;
    int lane = threadIdx.x & 31;
    if (w >= N_NODES) return;
    int beg = g_offs[w], end = g_offs[w + 1];
    float4 a0 = make_float4(0.f, 0.f, 0.f, 0.f);
    float4 a1 = make_float4(0.f, 0.f, 0.f, 0.f);
    int e = beg;
    for (; e + 1 < end; e += 2) {
        int s0 = g_ssrc[e], s1 = g_ssrc[e + 1];
        float4 v0 = E4[s0 * 32 + lane];
        float4 v1 = E4[s1 * 32 + lane];
        a0.x += v0.x; a0.y += v0.y; a0.z += v0.z; a0.w += v0.w;
        a1.x += v1.x; a1.y += v1.y; a1.z += v1.z; a1.w += v1.w;
    }
    if (e < end) {
        int s = g_ssrc[e];
        float4 v = E4[s * 32 + lane];
        a0.x += v.x; a0.y += v.y; a0.z += v.z; a0.w += v.w;
    }
    a0.x += a1.x; a0.y += a1.y; a0.z += a1.z; a0.w += a1.w;
    ((float4*)g_H)[w * 32 + lane] = a0;
}

// ---------------- phase 3: dual GEMV + LeakyReLU ------------------------------
// out[n][j] = lrelu(sum_k H[n][k]*W1[j][k] + b1[j])
//           + lrelu(sum_k (e[n][k]*H[n][k])*W2[j][k] + b2[j])
// Block: 512 threads, W1^T/W2^T in smem ([k][j] layout), 4 nodes per warp pass,
// lane l owns output columns {2l, 2l+1, 64+2l, 65+2l}; f32x2 packed FMAs.
__global__ void __launch_bounds__(GEMM_THREADS, 1)
k_gemm(const float4* __restrict__ E4,
       const float* __restrict__ W1, const float* __restrict__ b1,
       const float* __restrict__ W2, const float* __restrict__ b2,
       float* __restrict__ out) {
    extern __shared__ float smem[];
    float* sW1 = smem;              // [k][j]
    float* sW2 = smem + D * D;
    float* sB  = smem + 2 * D * D;  // b1 then b2
    int tid = threadIdx.x;
    for (int i = tid; i < D * D; i += GEMM_THREADS) {
        int j = i >> 7, k = i & 127;
        sW1[k * D + j] = W1[i];
        sW2[k * D + j] = W2[i];
    }
    if (tid < 2 * D) sB[tid] = (tid < D) ? b1[tid] : b2[tid - D];
    __syncthreads();

    const unsigned long long* sW1p = (const unsigned long long*)sW1;
    const unsigned long long* sW2p = (const unsigned long long*)sW2;
    const float4* H4 = (const float4*)g_H;

    int warp = tid >> 5, lane = tid & 31;
    int nwarps = gridDim.x * (GEMM_THREADS / 32);
    int gw = blockIdx.x * (GEMM_THREADS / 32) + warp;

    float2 bn0 = ((const float2*)sB)[lane];
    float2 bn1 = ((const float2*)sB)[32 + lane];
    float2 bi0 = ((const float2*)(sB + D))[lane];
    float2 bi1 = ((const float2*)(sB + D))[32 + lane];

    const int NGROUPS = N_NODES / 4;  // 12500
    for (int g = gw; g < NGROUPS; g += nwarps) {
        int n0 = g * 4;
        float4 h[4], m[4];
        #pragma unroll
        for (int i = 0; i < 4; i++) {
            int n = n0 + i;
            h[i] = H4[n * 32 + lane];
            float4 e = E4[n * 32 + lane];
            m[i] = make_float4(e.x * h[i].x, e.y * h[i].y, e.z * h[i].z, e.w * h[i].w);
        }
        unsigned long long aN0[4] = {0, 0, 0, 0}, aN1[4] = {0, 0, 0, 0};
        unsigned long long aI0[4] = {0, 0, 0, 0}, aI1[4] = {0, 0, 0, 0};

        for (int k4 = 0; k4 < 32; k4++) {
            #pragma unroll
            for (int c = 0; c < 4; c++) {
                int k = k4 * 4 + c;
                unsigned long long w1a = sW1p[k * 64 + lane];
                unsigned long long w1b = sW1p[k * 64 + 32 + lane];
                unsigned long long w2a = sW2p[k * 64 + lane];
                unsigned long long w2b = sW2p[k * 64 + 32 + lane];
                #pragma unroll
                for (int i = 0; i < 4; i++) {
                    float hk = __shfl_sync(0xffffffffu, f4c(h[i], c), k4);
                    float mk = __shfl_sync(0xffffffffu, f4c(m[i], c), k4);
                    unsigned long long hk2 = dup2(hk);
                    unsigned long long mk2 = dup2(mk);
                    fma2(aN0[i], hk2, w1a);
                    fma2(aN1[i], hk2, w1b);
                    fma2(aI0[i], mk2, w2a);
                    fma2(aI1[i], mk2, w2b);
                }
            }
        }

        #pragma unroll
        for (int i = 0; i < 4; i++) {
            int n = n0 + i;
            float2 n0v = unpack2(aN0[i]), n1v = unpack2(aN1[i]);
            float2 i0v = unpack2(aI0[i]), i1v = unpack2(aI1[i]);
            float2 r0, r1;
            r0.x = lrelu(n0v.x + bn0.x) + lrelu(i0v.x + bi0.x);
            r0.y = lrelu(n0v.y + bn0.y) + lrelu(i0v.y + bi0.y);
            r1.x = lrelu(n1v.x + bn1.x) + lrelu(i1v.x + bi1.x);
            r1.y = lrelu(n1v.y + bn1.y) + lrelu(i1v.y + bi1.y);
            ((float2*)out)[n * 64 + lane] = r0;
            ((float2*)out)[n * 64 + 32 + lane] = r1;
        }
    }
}

// ---------------- launch ------------------------------------------------------
extern "C" void kernel_launch(void* const* d_in, const int* in_sizes, int n_in,
                              void* d_out, int out_size) {
    const float* entity = (const float*)d_in[0];
    const float* W1 = (const float*)d_in[1];
    const float* b1 = (const float*)d_in[2];
    const float* W2 = (const float*)d_in[3];
    const float* b2 = (const float*)d_in[4];
    const int*   src = (const int*)d_in[5];
    const int*   dst = (const int*)d_in[6];
    float* out = (float*)d_out;

    cudaFuncSetAttribute(k_gemm, cudaFuncAttributeMaxDynamicSharedMemorySize, GEMM_SMEM);

    k_zero<<<(N_NODES + 255) / 256, 256>>>();
    k_count<<<(N_EDGES + 255) / 256, 256>>>(dst);
    k_scan<<<1, 1024>>>();
    k_fill<<<(N_EDGES + 255) / 256, 256>>>(src, dst);
    k_gather<<<(N_NODES * 32 + 255) / 256, 256>>>((const float4*)entity);
    k_gemm<<<148, GEMM_THREADS, GEMM_SMEM>>>((const float4*)entity, W1, b1, W2, b2, out);
}

// round 2
// speedup vs baseline: 1.3254x; 1.3254x over previous
#include <cuda_runtime.h>

#define N_NODES 50000
#define N_EDGES 1600000
#define D 128
#define SLOPE 0.01f
#define SCAN_BLOCKS 49            // 49*1024 = 50176 >= 50001
#define GT 128                    // gemm threads per block
#define NTILES ((N_NODES + 63) / 64)
typedef unsigned long long ull;

// ---------------- scratch (device globals) -----------------------------------
__device__ int    g_cnt[N_NODES];
__device__ int    g_offs[N_NODES + 1];   // per-scan-block partial exclusive
__device__ int    g_cursor[N_NODES];
__device__ int    g_bsum[SCAN_BLOCKS];   // exclusive scan of scan-block totals
__device__ int    g_ssrc[N_EDGES];
__device__ float4 g_H4[N_NODES * 32];
__device__ float  g_W1T[D * D];          // [k][j]
__device__ float  g_W2T[D * D];

// ---------------- helpers -----------------------------------------------------
__device__ __forceinline__ void fma2(ull& acc, ull a, ull b) {
    asm("fma.rn.f32x2 %0, %1, %2, %0;" : "+l"(acc) : "l"(a), "l"(b));
}
__device__ __forceinline__ ull dup2(float x) {
    ull r; asm("mov.b64 %0, {%1, %1};" : "=l"(r) : "f"(x)); return r;
}
__device__ __forceinline__ float2 unpack2(ull v) {
    float2 f; asm("mov.b64 {%0, %1}, %2;" : "=f"(f.x), "=f"(f.y) : "l"(v)); return f;
}
__device__ __forceinline__ float lrelu(float x) { return fmaxf(x, SLOPE * x); }

// ---------------- weight transpose (once) -------------------------------------
__global__ void k_wt(const float* __restrict__ W1, const float* __restrict__ W2) {
    __shared__ float t[32][33];
    const float* W = blockIdx.z ? W2 : W1;
    float* T = blockIdx.z ? g_W2T : g_W1T;
    int bx = blockIdx.x * 32, by = blockIdx.y * 32;
    int tx = threadIdx.x;
    for (int i = threadIdx.y; i < 32; i += 8)
        t[i][tx] = W[(by + i) * D + bx + tx];
    __syncthreads();
    for (int i = threadIdx.y; i < 32; i += 8)
        T[(bx + i) * D + by + tx] = t[tx][i];
}

// ---------------- CSR build ----------------------------------------------------
__global__ void k_zero() {
    int i = blockIdx.x * blockDim.x + threadIdx.x;
    if (i < N_NODES) g_cnt[i] = 0;
}

__global__ void k_count(const int* __restrict__ dst) {
    int i = blockIdx.x * blockDim.x + threadIdx.x;
    if (i < N_EDGES) atomicAdd(&g_cnt[dst[i]], 1);
}

__global__ void k_scan1() {
    __shared__ int wsum[32];
    int tid = threadIdx.x, lane = tid & 31, wid = tid >> 5;
    int i = blockIdx.x * 1024 + tid;
    int v = (i < N_NODES) ? g_cnt[i] : 0;
    int x = v;
    #pragma unroll
    for (int o = 1; o < 32; o <<= 1) {
        int y = __shfl_up_sync(0xffffffffu, x, o);
        if (lane >= o) x += y;
    }
    if (lane == 31) wsum[wid] = x;
    __syncthreads();
    if (wid == 0) {
        int s = wsum[lane];
        #pragma unroll
        for (int o = 1; o < 32; o <<= 1) {
            int y = __shfl_up_sync(0xffffffffu, s, o);
            if (lane >= o) s += y;
        }
        wsum[lane] = s;
    }
    __syncthreads();
    int excl = x - v + (wid ? wsum[wid - 1] : 0);
    if (i <= N_NODES) g_offs[i] = excl;
    if (i < N_NODES) g_cursor[i] = excl;
    if (tid == 1023) g_bsum[blockIdx.x] = excl + v;
}

__global__ void k_scan2() {
    __shared__ int w0tot;
    int t = threadIdx.x, lane = t & 31;
    int v = (t < SCAN_BLOCKS) ? g_bsum[t] : 0;
    int x = v;
    #pragma unroll
    for (int o = 1; o < 32; o <<= 1) {
        int y = __shfl_up_sync(0xffffffffu, x, o);
        if (lane >= o) x += y;
    }
    if (t == 31) w0tot = x;
    __syncthreads();
    int excl = x - v + ((t >= 32) ? w0tot : 0);
    if (t < SCAN_BLOCKS) g_bsum[t] = excl;
}

__global__ void k_fill(const int* __restrict__ src, const int* __restrict__ dst) {
    int i = blockIdx.x * blockDim.x + threadIdx.x;
    if (i < N_EDGES) {
        int d = dst[i];
        int p = atomicAdd(&g_cursor[d], 1) + g_bsum[d >> 10];
        g_ssrc[p] = src[i];
    }
}

// ---------------- gather-sum (one warp per node) --------------------------------
__global__ void k_gather(const float4* __restrict__ E4) {
    int w = (blockIdx.x * blockDim.x + threadIdx.x) >> 5;
    int lane = threadIdx.x & 31;
    if (w >= N_NODES) return;
    int beg = g_offs[w] + g_bsum[w >> 10];
    int end = g_offs[w + 1] + g_bsum[(w + 1) >> 10];
    float4 a0 = make_float4(0.f, 0.f, 0.f, 0.f);
    float4 a1 = a0, a2 = a0, a3 = a0;
    int e = beg;
    for (; e + 3 < end; e += 4) {
        int s0 = g_ssrc[e], s1 = g_ssrc[e + 1], s2 = g_ssrc[e + 2], s3 = g_ssrc[e + 3];
        float4 v0 = E4[s0 * 32 + lane];
        float4 v1 = E4[s1 * 32 + lane];
        float4 v2 = E4[s2 * 32 + lane];
        float4 v3 = E4[s3 * 32 + lane];
        a0.x += v0.x; a0.y += v0.y; a0.z += v0.z; a0.w += v0.w;
        a1.x += v1.x; a1.y += v1.y; a1.z += v1.z; a1.w += v1.w;
        a2.x += v2.x; a2.y += v2.y; a2.z += v2.z; a2.w += v2.w;
        a3.x += v3.x; a3.y += v3.y; a3.z += v3.z; a3.w += v3.w;
    }
    for (; e < end; e++) {
        int s = g_ssrc[e];
        float4 v = E4[s * 32 + lane];
        a0.x += v.x; a0.y += v.y; a0.z += v.z; a0.w += v.w;
    }
    a0.x += a1.x + a2.x + a3.x;
    a0.y += a1.y + a2.y + a3.y;
    a0.z += a1.z + a2.z + a3.z;
    a0.w += a1.w + a2.w + a3.w;
    g_H4[w * 32 + lane] = a0;
}

// ---------------- dual GEMV + LeakyReLU (register-blocked) ----------------------
// Persistent blocks. Per block: 64-node tile; sW1/sW2 [k][j] 64KB each,
// sH/sM [k][n] transposed 16KB each (total 192KB). Thread (grp, lane16):
// 8 nodes (grp*8..+7) x 16 cols (8 on each branch, cols j0..j0+7).
__device__ __forceinline__ void stepf(float h, float m,
                                      ulonglong2 w1a, ulonglong2 w1b,
                                      ulonglong2 w2a, ulonglong2 w2b,
                                      ull* aN, ull* aI) {
    ull h2 = dup2(h), m2 = dup2(m);
    fma2(aN[0], h2, w1a.x); fma2(aN[1], h2, w1a.y);
    fma2(aN[2], h2, w1b.x); fma2(aN[3], h2, w1b.y);
    fma2(aI[0], m2, w2a.x); fma2(aI[1], m2, w2a.y);
    fma2(aI[2], m2, w2b.x); fma2(aI[3], m2, w2b.y);
}

#define GEMM_SMEM ((2 * D * D + 2 * D * 64) * 4)

__global__ void __launch_bounds__(GT, 1)
k_gemm(const float4* __restrict__ E4,
       const float* __restrict__ b1, const float* __restrict__ b2,
       float* __restrict__ out) {
    extern __shared__ float sm[];
    float* sW1 = sm;                  // [k][j] 16384
    float* sW2 = sm + D * D;          // 16384
    float* sH  = sm + 2 * D * D;      // [k][n] 8192
    float* sM  = sH + D * 64;         // 8192
    int tid = threadIdx.x;
    int lane16 = tid & 15, grp = tid >> 4;
    int j0 = lane16 * 8;

    {   // weights into smem once (coalesced, conflict-free)
        float4* d1 = (float4*)sW1; const float4* s1 = (const float4*)g_W1T;
        float4* d2 = (float4*)sW2; const float4* s2 = (const float4*)g_W2T;
        #pragma unroll
        for (int i = 0; i < D * D / 4 / GT; i++) {
            d1[i * GT + tid] = s1[i * GT + tid];
            d2[i * GT + tid] = s2[i * GT + tid];
        }
    }
    float4 b1a = *(const float4*)&b1[j0], b1b = *(const float4*)&b1[j0 + 4];
    float4 b2a = *(const float4*)&b2[j0], b2b = *(const float4*)&b2[j0 + 4];

    const ulonglong2* W1p = (const ulonglong2*)sW1;   // row = 32 ulonglong2
    const ulonglong2* W2p = (const ulonglong2*)sW2;
    const float4* Hp = (const float4*)sH;             // row = 16 float4
    const float4* Mp = (const float4*)sM;
    int wj = lane16 * 2;
    int hj = grp * 2;

    for (int t = blockIdx.x; t < NTILES; t += gridDim.x) {
        int nbase = t * 64;
        __syncthreads();  // prior tile fully consumed
        // ---- load H/E tile, transpose into sH/sM ----
        #pragma unroll
        for (int it = 0; it < 8; it++) {
            int idx = it * GT + tid;          // 0..1023
            int n = idx & 63, c8 = idx >> 6;  // c8: 0..15
            int gn = nbase + n;
            float4 h0, h1, e0, e1;
            if (gn < N_NODES) {
                h0 = g_H4[gn * 32 + c8 * 2]; h1 = g_H4[gn * 32 + c8 * 2 + 1];
                e0 = E4[gn * 32 + c8 * 2];   e1 = E4[gn * 32 + c8 * 2 + 1];
            } else {
                h0 = h1 = e0 = e1 = make_float4(0.f, 0.f, 0.f, 0.f);
            }
            int k0 = c8 * 8;
            sH[(k0 + 0) * 64 + n] = h0.x; sH[(k0 + 1) * 64 + n] = h0.y;
            sH[(k0 + 2) * 64 + n] = h0.z; sH[(k0 + 3) * 64 + n] = h0.w;
            sH[(k0 + 4) * 64 + n] = h1.x; sH[(k0 + 5) * 64 + n] = h1.y;
            sH[(k0 + 6) * 64 + n] = h1.z; sH[(k0 + 7) * 64 + n] = h1.w;
            sM[(k0 + 0) * 64 + n] = e0.x * h0.x; sM[(k0 + 1) * 64 + n] = e0.y * h0.y;
            sM[(k0 + 2) * 64 + n] = e0.z * h0.z; sM[(k0 + 3) * 64 + n] = e0.w * h0.w;
            sM[(k0 + 4) * 64 + n] = e1.x * h1.x; sM[(k0 + 5) * 64 + n] = e1.y * h1.y;
            sM[(k0 + 6) * 64 + n] = e1.z * h1.z; sM[(k0 + 7) * 64 + n] = e1.w * h1.w;
        }
        __syncthreads();

        ull accN[8][4], accI[8][4];
        #pragma unroll
        for (int i = 0; i < 8; i++)
            #pragma unroll
            for (int c = 0; c < 4; c++) { accN[i][c] = 0ull; accI[i][c] = 0ull; }

        ulonglong2 w1aA, w1bA, w2aA, w2bA; float4 haA, hbA, maA, mbA;
        ulonglong2 w1aB, w1bB, w2aB, w2bB; float4 haB, hbB, maB, mbB;

#define LOADK(S, kk)                                                            \
        w1a##S = W1p[(kk) * 32 + wj]; w1b##S = W1p[(kk) * 32 + wj + 1];        \
        w2a##S = W2p[(kk) * 32 + wj]; w2b##S = W2p[(kk) * 32 + wj + 1];        \
        ha##S = Hp[(kk) * 16 + hj];   hb##S = Hp[(kk) * 16 + hj + 1];          \
        ma##S = Mp[(kk) * 16 + hj];   mb##S = Mp[(kk) * 16 + hj + 1];

#define COMPK(S)                                                                \
        stepf(ha##S.x, ma##S.x, w1a##S, w1b##S, w2a##S, w2b##S, accN[0], accI[0]); \
        stepf(ha##S.y, ma##S.y, w1a##S, w1b##S, w2a##S, w2b##S, accN[1], accI[1]); \
        stepf(ha##S.z, ma##S.z, w1a##S, w1b##S, w2a##S, w2b##S, accN[2], accI[2]); \
        stepf(ha##S.w, ma##S.w, w1a##S, w1b##S, w2a##S, w2b##S, accN[3], accI[3]); \
        stepf(hb##S.x, mb##S.x, w1a##S, w1b##S, w2a##S, w2b##S, accN[4], accI[4]); \
        stepf(hb##S.y, mb##S.y, w1a##S, w1b##S, w2a##S, w2b##S, accN[5], accI[5]); \
        stepf(hb##S.z, mb##S.z, w1a##S, w1b##S, w2a##S, w2b##S, accN[6], accI[6]); \
        stepf(hb##S.w, mb##S.w, w1a##S, w1b##S, w2a##S, w2b##S, accN[7], accI[7]);

        LOADK(A, 0)
        #pragma unroll 4
        for (int k = 0; k < D; k += 2) {
            LOADK(B, k + 1)
            COMPK(A)
            int k2 = (k + 2) & (D - 1);
            LOADK(A, k2)
            COMPK(B)
        }
#undef LOADK
#undef COMPK

        // ---- epilogue ----
        float b1r[8] = {b1a.x, b1a.y, b1a.z, b1a.w, b1b.x, b1b.y, b1b.z, b1b.w};
        float b2r[8] = {b2a.x, b2a.y, b2a.z, b2a.w, b2b.x, b2b.y, b2b.z, b2b.w};
        #pragma unroll
        for (int i = 0; i < 8; i++) {
            int n = nbase + grp * 8 + i;
            if (n < N_NODES) {
                float o[8];
                #pragma unroll
                for (int c = 0; c < 4; c++) {
                    float2 vN = unpack2(accN[i][c]);
                    float2 vI = unpack2(accI[i][c]);
                    o[2 * c]     = lrelu(vN.x + b1r[2 * c])     + lrelu(vI.x + b2r[2 * c]);
                    o[2 * c + 1] = lrelu(vN.y + b1r[2 * c + 1]) + lrelu(vI.y + b2r[2 * c + 1]);
                }
                *(float4*)&out[n * D + j0]     = make_float4(o[0], o[1], o[2], o[3]);
                *(float4*)&out[n * D + j0 + 4] = make_float4(o[4], o[5], o[6], o[7]);
            }
        }
    }
}

// ---------------- launch --------------------------------------------------------
extern "C" void kernel_launch(void* const* d_in, const int* in_sizes, int n_in,
                              void* d_out, int out_size) {
    const float* entity = (const float*)d_in[0];
    const float* W1 = (const float*)d_in[1];
    const float* b1 = (const float*)d_in[2];
    const float* W2 = (const float*)d_in[3];
    const float* b2 = (const float*)d_in[4];
    const int*   src = (const int*)d_in[5];
    const int*   dst = (const int*)d_in[6];
    float* out = (float*)d_out;
    const float4* E4 = (const float4*)entity;

    cudaFuncSetAttribute(k_gemm, cudaFuncAttributeMaxDynamicSharedMemorySize, GEMM_SMEM);

    k_wt<<<dim3(4, 4, 2), dim3(32, 8)>>>(W1, W2);
    k_zero<<<(N_NODES + 255) / 256, 256>>>();
    k_count<<<(N_EDGES + 255) / 256, 256>>>(dst);
    k_scan1<<<SCAN_BLOCKS, 1024>>>();
    k_scan2<<<1, 64>>>();
    k_fill<<<(N_EDGES + 255) / 256, 256>>>(src, dst);
    k_gather<<<(N_NODES * 32 + 255) / 256, 256>>>(E4);
    k_gemm<<<148, GT, GEMM_SMEM>>>(E4, b1, b2, out);
}